// round 4
// baseline (speedup 1.0000x reference)
#include <cuda_runtime.h>
#include <cuda_bf16.h>

// Fused 3-block transformer encoder, one CTA (512 threads) per batch sample.
// B=4096, L=50, D=200, NUM_HEADS=1, NB=3. All fp32.

#define TL 50
#define TD 200
#define TNB 3
#define XS 204            // activation row stride (floats)
#define SCS 52            // scores row stride
#define KC 8              // weight k-chunk rows staged in smem
#define NCHUNK 25         // 200 / 8
#define NTHR 512
#define NEGV (-4294967295.0f)

// smem layout (floats)
#define OFF_XS   0
#define OFF_QS   (TL*XS)
#define OFF_KS   (2*TL*XS)
#define OFF_VS   (3*TL*XS)
#define OFF_SC   (4*TL*XS)
#define OFF_WB0  (OFF_SC + TL*SCS)
#define OFF_WB1  (OFF_WB0 + KC*TD)
#define OFF_BIAS (OFF_WB1 + KC*TD)
#define OFF_KM   (OFF_BIAS + 7*TD)
#define OFF_QM   (OFF_KM + TL)
#define OFF_TOK  (OFF_QM + TL)
#define SMEM_FLOATS (OFF_TOK + TL + 2)
#define SMEM_BYTES  (SMEM_FLOATS * 4)

// ---------------------------------------------------------------------------
// GEMM: C[50,200] = act(A[50,200] @ W[200,200] + b)
// 512 threads; tid<500 active with 5-row x 4-col tiles.
// Weights double-buffered in smem, KC=8 rows per chunk, 1 sync per chunk.
// ---------------------------------------------------------------------------
template<bool RELU>
__device__ __forceinline__ void gemm200(
    const float* __restrict__ A, const float* __restrict__ Wg,
    const float* __restrict__ bvec, float* __restrict__ Cdst,
    float* __restrict__ wb0, float* __restrict__ wb1,
    int tid, int r0, int c0, bool active)
{
    float acc[5][4];
#pragma unroll
    for (int i = 0; i < 5; i++)
#pragma unroll
        for (int j = 0; j < 4; j++) acc[i][j] = 0.f;

    const bool ld = (tid < 400);           // 400 float4 per KC-row chunk
    float4 p;
    if (ld) p = ((const float4*)Wg)[tid];
    if (ld) ((float4*)wb0)[tid] = p;
    __syncthreads();

    for (int c = 0; c < NCHUNK; ++c) {
        float* wb = (c & 1) ? wb1 : wb0;
        float* wn = (c & 1) ? wb0 : wb1;
        if (c + 1 < NCHUNK && ld)
            p = ((const float4*)(Wg + (c + 1) * KC * TD))[tid];

        const int kb = c * KC;
#pragma unroll
        for (int h = 0; h < 2; ++h) {
            float4 av[5];
#pragma unroll
            for (int i = 0; i < 5; i++)
                av[i] = *(const float4*)(A + (r0 + i) * XS + kb + h * 4);

            float4 w;
            w = *(const float4*)(wb + (h * 4 + 0) * TD + c0);
#pragma unroll
            for (int i = 0; i < 5; i++) {
                acc[i][0] = fmaf(av[i].x, w.x, acc[i][0]);
                acc[i][1] = fmaf(av[i].x, w.y, acc[i][1]);
                acc[i][2] = fmaf(av[i].x, w.z, acc[i][2]);
                acc[i][3] = fmaf(av[i].x, w.w, acc[i][3]);
            }
            w = *(const float4*)(wb + (h * 4 + 1) * TD + c0);
#pragma unroll
            for (int i = 0; i < 5; i++) {
                acc[i][0] = fmaf(av[i].y, w.x, acc[i][0]);
                acc[i][1] = fmaf(av[i].y, w.y, acc[i][1]);
                acc[i][2] = fmaf(av[i].y, w.z, acc[i][2]);
                acc[i][3] = fmaf(av[i].y, w.w, acc[i][3]);
            }
            w = *(const float4*)(wb + (h * 4 + 2) * TD + c0);
#pragma unroll
            for (int i = 0; i < 5; i++) {
                acc[i][0] = fmaf(av[i].z, w.x, acc[i][0]);
                acc[i][1] = fmaf(av[i].z, w.y, acc[i][1]);
                acc[i][2] = fmaf(av[i].z, w.z, acc[i][2]);
                acc[i][3] = fmaf(av[i].z, w.w, acc[i][3]);
            }
            w = *(const float4*)(wb + (h * 4 + 3) * TD + c0);
#pragma unroll
            for (int i = 0; i < 5; i++) {
                acc[i][0] = fmaf(av[i].w, w.x, acc[i][0]);
                acc[i][1] = fmaf(av[i].w, w.y, acc[i][1]);
                acc[i][2] = fmaf(av[i].w, w.z, acc[i][2]);
                acc[i][3] = fmaf(av[i].w, w.w, acc[i][3]);
            }
        }

        if (c + 1 < NCHUNK && ld) ((float4*)wn)[tid] = p;
        __syncthreads();
    }

    if (active) {
#pragma unroll
        for (int i = 0; i < 5; i++)
#pragma unroll
            for (int j = 0; j < 4; j++) {
                float v = acc[i][j] + bvec[c0 + j];
                if (RELU) v = fmaxf(v, 0.f);
                Cdst[(r0 + i) * XS + c0 + j] = v;
            }
    }
}

__global__ __launch_bounds__(NTHR, 1)
void xformer3_kernel(
    const int* __restrict__ tokens, const float* __restrict__ emb,
    const float* __restrict__ Wq, const float* __restrict__ bq,
    const float* __restrict__ Wk, const float* __restrict__ bk,
    const float* __restrict__ Wv, const float* __restrict__ bv,
    const float* __restrict__ W1, const float* __restrict__ b1,
    const float* __restrict__ W2, const float* __restrict__ b2,
    const float* __restrict__ lng, const float* __restrict__ lnb,
    float* __restrict__ out)
{
    extern __shared__ float sm[];
    float* xs   = sm + OFF_XS;
    float* qs   = sm + OFF_QS;
    float* ks   = sm + OFF_KS;
    float* vs   = sm + OFF_VS;
    float* sc   = sm + OFF_SC;
    float* wb0  = sm + OFF_WB0;
    float* wb1  = sm + OFF_WB1;
    float* bias = sm + OFF_BIAS;
    float* km   = sm + OFF_KM;
    float* qm   = sm + OFF_QM;
    int*   tok  = (int*)(sm + OFF_TOK);

    const int tid  = threadIdx.x;
    const int lane = tid & 31;
    const int wid  = tid >> 5;
    const int b    = blockIdx.x;

    const bool active = (tid < 500);
    const int r0 = active ? (tid % 10) * 5 : 0;   // 5 output rows
    const int c0 = active ? (tid / 10) * 4 : 0;   // 4 output cols

    // ---- token load + embedding gather ----
    if (tid < TL) tok[tid] = tokens[b * TL + tid];
    __syncthreads();
    for (int i = tid; i < TL * (TD / 4); i += NTHR) {
        int r = i / (TD / 4), c4 = i % (TD / 4);
        float4 v = *(const float4*)(emb + (size_t)tok[r] * TD + c4 * 4);
        *(float4*)(xs + r * XS + c4 * 4) = v;
    }
    __syncthreads();

    for (int blk = 0; blk < TNB; ++blk) {
        // ---- biases / LN params into smem ----
        {
            const int boff = blk * TD;
            for (int j = tid; j < TD; j += NTHR) {
                bias[0 * TD + j] = bq [boff + j];
                bias[1 * TD + j] = bk [boff + j];
                bias[2 * TD + j] = bv [boff + j];
                bias[3 * TD + j] = b1 [boff + j];
                bias[4 * TD + j] = b2 [boff + j];
                bias[5 * TD + j] = lng[boff + j];
                bias[6 * TD + j] = lnb[boff + j];
            }
        }
        // ---- key / query masks: sum(x_row)==0 ----
        for (int r = wid; r < TL; r += 16) {
            float s = 0.f;
#pragma unroll
            for (int t = 0; t < 7; t++) {
                int c = lane + 32 * t;
                if (c < TD) s += xs[r * XS + c];
            }
#pragma unroll
            for (int o = 16; o; o >>= 1) s += __shfl_xor_sync(0xffffffffu, s, o);
            if (lane == 0) {
                float z = (s == 0.f) ? 1.f : 0.f;
                km[r] = z;
                qm[r] = 1.f - z;
            }
        }
        __syncthreads();

        // ---- Q, K, V ----
        gemm200<true>(xs, Wq + blk * TD * TD, bias + 0 * TD, qs, wb0, wb1, tid, r0, c0, active);
        gemm200<true>(xs, Wk + blk * TD * TD, bias + 1 * TD, ks, wb0, wb1, tid, r0, c0, active);
        gemm200<true>(xs, Wv + blk * TD * TD, bias + 2 * TD, vs, wb0, wb1, tid, r0, c0, active);
        __syncthreads();

        // ---- scores = Q K^T * scale, key mask -> NEG ----
        if (active) {
            const int q0 = r0;             // 5 query rows
            const int kk = tid / 10;       // 1 key
            float acc5[5] = {0.f, 0.f, 0.f, 0.f, 0.f};
            for (int d = 0; d < TD; d += 4) {
                float4 kv = *(const float4*)(ks + kk * XS + d);
#pragma unroll
                for (int i = 0; i < 5; i++) {
                    float4 qv = *(const float4*)(qs + (q0 + i) * XS + d);
                    acc5[i] = fmaf(qv.x, kv.x, acc5[i]);
                    acc5[i] = fmaf(qv.y, kv.y, acc5[i]);
                    acc5[i] = fmaf(qv.z, kv.z, acc5[i]);
                    acc5[i] = fmaf(qv.w, kv.w, acc5[i]);
                }
            }
            const float scale = 0.07071067811865475f;  // 1/sqrt(200)
            const bool masked = (km[kk] != 0.f);
#pragma unroll
            for (int i = 0; i < 5; i++) {
                float v = acc5[i] * scale;
                if (masked) v = NEGV;
                sc[(q0 + i) * SCS + kk] = v;
            }
        }
        __syncthreads();

        // ---- softmax over keys (50), then * qmask ----
        for (int r = wid; r < TL; r += 16) {
            float* row = sc + r * SCS;
            float v0 = row[lane];
            float v1 = (lane < TL - 32) ? row[lane + 32] : -3.4e38f;
            float m = fmaxf(v0, v1);
#pragma unroll
            for (int o = 16; o; o >>= 1) m = fmaxf(m, __shfl_xor_sync(0xffffffffu, m, o));
            float e0 = __expf(v0 - m);
            float e1 = (lane < TL - 32) ? __expf(v1 - m) : 0.f;
            float s = e0 + e1;
#pragma unroll
            for (int o = 16; o; o >>= 1) s += __shfl_xor_sync(0xffffffffu, s, o);
            float f = qm[r] / s;
            row[lane] = e0 * f;
            if (lane < TL - 32) row[lane + 32] = e1 * f;
        }
        __syncthreads();

        // ---- x += attn @ V ----
        if (active) {
            float acc[5][4];
#pragma unroll
            for (int i = 0; i < 5; i++)
#pragma unroll
                for (int j = 0; j < 4; j++) acc[i][j] = 0.f;
#pragma unroll 5
            for (int k = 0; k < TL; k++) {
                float4 vv = *(const float4*)(vs + k * XS + c0);
#pragma unroll
                for (int i = 0; i < 5; i++) {
                    float a = sc[(r0 + i) * SCS + k];
                    acc[i][0] = fmaf(a, vv.x, acc[i][0]);
                    acc[i][1] = fmaf(a, vv.y, acc[i][1]);
                    acc[i][2] = fmaf(a, vv.z, acc[i][2]);
                    acc[i][3] = fmaf(a, vv.w, acc[i][3]);
                }
            }
#pragma unroll
            for (int i = 0; i < 5; i++)
#pragma unroll
                for (int j = 0; j < 4; j++)
                    xs[(r0 + i) * XS + c0 + j] += acc[i][j];
        }
        __syncthreads();

        // ---- FFN: t = relu(x W1 + b1); h = t W2 + b2 ----
        gemm200<true >(xs, W1 + blk * TD * TD, bias + 3 * TD, qs, wb0, wb1, tid, r0, c0, active);
        gemm200<false>(qs, W2 + blk * TD * TD, bias + 4 * TD, ks, wb0, wb1, tid, r0, c0, active);
        __syncthreads();

        // ---- LayerNorm(h)*g + b + x -> x ----
        {
            const float* g  = bias + 5 * TD;
            const float* lb = bias + 6 * TD;
            for (int r = wid; r < TL; r += 16) {
                float xv[7];
                float s = 0.f;
#pragma unroll
                for (int t = 0; t < 7; t++) {
                    int c = lane + 32 * t;
                    xv[t] = (c < TD) ? ks[r * XS + c] : 0.f;
                    s += xv[t];
                }
#pragma unroll
                for (int o = 16; o; o >>= 1) s += __shfl_xor_sync(0xffffffffu, s, o);
                float mu = s * (1.f / TD);
                float s2 = 0.f;
#pragma unroll
                for (int t = 0; t < 7; t++) {
                    int c = lane + 32 * t;
                    float d = (c < TD) ? (xv[t] - mu) : 0.f;
                    s2 += d * d;
                }
#pragma unroll
                for (int o = 16; o; o >>= 1) s2 += __shfl_xor_sync(0xffffffffu, s2, o);
                float inv = rsqrtf(s2 * (1.f / TD) + 1e-8f);
#pragma unroll
                for (int t = 0; t < 7; t++) {
                    int c = lane + 32 * t;
                    if (c < TD) {
                        int idx = r * XS + c;
                        xs[idx] = (xv[t] - mu) * inv * g[c] + lb[c] + xs[idx];
                    }
                }
            }
        }
        __syncthreads();
    }

    // ---- store result ----
    for (int i = tid; i < TL * (TD / 4); i += NTHR) {
        int r = i / (TD / 4), c4 = i % (TD / 4);
        *(float4*)(out + (size_t)b * TL * TD + r * TD + c4 * 4) =
            *(const float4*)(xs + r * XS + c4 * 4);
    }
}

extern "C" void kernel_launch(void* const* d_in, const int* in_sizes, int n_in,
                              void* d_out, int out_size)
{
    const int*   tokens = (const int*)  d_in[0];
    const float* emb    = (const float*)d_in[1];
    const float* Wq     = (const float*)d_in[2];
    const float* bq     = (const float*)d_in[3];
    const float* Wk     = (const float*)d_in[4];
    const float* bk     = (const float*)d_in[5];
    const float* Wv     = (const float*)d_in[6];
    const float* bv     = (const float*)d_in[7];
    const float* W1     = (const float*)d_in[8];
    const float* b1     = (const float*)d_in[9];
    const float* W2     = (const float*)d_in[10];
    const float* b2     = (const float*)d_in[11];
    const float* lng    = (const float*)d_in[12];
    const float* lnb    = (const float*)d_in[13];
    float*       out    = (float*)d_out;

    const int B = in_sizes[0] / TL;

    cudaFuncSetAttribute(xformer3_kernel,
                         cudaFuncAttributeMaxDynamicSharedMemorySize, SMEM_BYTES);
    xformer3_kernel<<<B, NTHR, SMEM_BYTES>>>(
        tokens, emb, Wq, bq, Wk, bk, Wv, bv, W1, b1, W2, b2, lng, lnb, out);
}